// round 11
// baseline (speedup 1.0000x reference)
#include <cuda_runtime.h>
#include <cuda_bf16.h>
#include <math.h>
#include <stdint.h>

#define LL 1024
#define BB 128
#define DD 256
#define HH 256

#define XN (LL * BB * DD)
#define WN (HH * DD)

// Pre-split bf16 scratch (static device arrays — allowed)
__device__ __align__(16) __nv_bfloat16 g_xhi[XN];
__device__ __align__(16) __nv_bfloat16 g_xlo[XN];
__device__ __align__(16) __nv_bfloat16 g_whi[WN];
__device__ __align__(16) __nv_bfloat16 g_wlo[WN];

__device__ __forceinline__ uint32_t smem_u32(const void* p) {
    uint32_t a;
    asm("{ .reg .u64 t; cvta.to.shared.u64 t, %1; cvt.u32.u64 %0, t; }"
        : "=r"(a) : "l"(p));
    return a;
}

// Packed f32x2 ops
__device__ __forceinline__ unsigned long long ffma2(
    unsigned long long a, unsigned long long b, unsigned long long c)
{
    unsigned long long d;
    asm("fma.rn.f32x2 %0, %1, %2, %3;" : "=l"(d) : "l"(a), "l"(b), "l"(c));
    return d;
}
__device__ __forceinline__ unsigned long long addf2(
    unsigned long long a, unsigned long long b)
{
    unsigned long long d;
    asm("add.rn.f32x2 %0, %1, %2;" : "=l"(d) : "l"(a), "l"(b));
    return d;
}
__device__ __forceinline__ float upk_sum(unsigned long long p)
{
    float lo, hi;
    asm("mov.b64 {%0, %1}, %2;" : "=f"(lo), "=f"(hi) : "l"(p));
    return lo + hi;
}

// fast tanh: 1 - 2/(e^{2x}+1); exact at both saturations, rel err ~1e-6
__device__ __forceinline__ float fast_tanh(float x)
{
    float e = __expf(x + x);
    float r;
    asm("rcp.approx.f32 %0, %1;" : "=f"(r) : "f"(e + 1.0f));
    return fmaf(-2.0f, r, 1.0f);
}

__device__ __forceinline__ void split2(float a, float b, uint32_t& h, uint32_t& l) {
    __nv_bfloat16 ha = __float2bfloat16(a);
    __nv_bfloat16 hb = __float2bfloat16(b);
    float ra = a - __bfloat162float(ha);
    float rb = b - __bfloat162float(hb);
    __nv_bfloat16 la = __float2bfloat16(ra);
    __nv_bfloat16 lb = __float2bfloat16(rb);
    h = (uint32_t)reinterpret_cast<unsigned short&>(ha) |
        ((uint32_t)reinterpret_cast<unsigned short&>(hb) << 16);
    l = (uint32_t)reinterpret_cast<unsigned short&>(la) |
        ((uint32_t)reinterpret_cast<unsigned short&>(lb) << 16);
}

// cp.async helpers
__device__ __forceinline__ void cp16(uint32_t s, const void* g) {
    asm volatile("cp.async.cg.shared.global [%0], [%1], 16;" :: "r"(s), "l"(g));
}
#define CP_COMMIT() asm volatile("cp.async.commit_group;" ::: "memory")
template <int N>
__device__ __forceinline__ void cp_wait() {
    asm volatile("cp.async.wait_group %0;" :: "n"(N) : "memory");
}

// ====================================================================
// Kernel 0: one-shot fp32 -> split-bf16 (hi, lo) for X and Wx.
// ====================================================================
#define CV_JOBS ((XN + WN) / 4)

__global__ __launch_bounds__(256) void convert_kernel(
    const float* __restrict__ X, const float* __restrict__ Wx)
{
    int i = blockIdx.x * 256 + threadIdx.x;
    if (i >= CV_JOBS) return;
    float4 v;
    if (i < XN / 4) v = ((const float4*)X)[i];
    else            v = ((const float4*)Wx)[i - XN / 4];
    uint2 hi, lo;
    split2(v.x, v.y, hi.x, lo.x);
    split2(v.z, v.w, hi.y, lo.y);
    if (i < XN / 4) {
        *(uint2*)(g_xhi + (size_t)i * 4) = hi;
        *(uint2*)(g_xlo + (size_t)i * 4) = lo;
    } else {
        size_t o = (size_t)(i - XN / 4) * 4;
        *(uint2*)(g_whi + o) = hi;
        *(uint2*)(g_wlo + o) = lo;
    }
}

// ====================================================================
// Kernel 1: xproj GEMM, mma.sync bf16 split-3, double-buffered cp.async.
// ====================================================================
#define XP_STRIDE_B 144
#define XP_TILE_B   (128 * XP_STRIDE_B)
#define XP_AHI 0
#define XP_ALO XP_TILE_B
#define XP_WHI (2 * XP_TILE_B)
#define XP_WLO (3 * XP_TILE_B)
#define XP_SMEM (4 * XP_TILE_B)          // one buffer: 73728
#define XP_SMEM2 (2 * XP_SMEM)           // double buffer: 147456

__device__ __forceinline__ void ldm_x4(uint32_t& r0, uint32_t& r1,
                                       uint32_t& r2, uint32_t& r3, uint32_t addr) {
    asm volatile("ldmatrix.sync.aligned.m8n8.x4.shared.b16 {%0,%1,%2,%3}, [%4];"
                 : "=r"(r0), "=r"(r1), "=r"(r2), "=r"(r3) : "r"(addr));
}

__device__ __forceinline__ void mma16816(float* c, const uint32_t* a,
                                         uint32_t b0, uint32_t b1) {
    asm volatile(
        "mma.sync.aligned.m16n8k16.row.col.f32.bf16.bf16.f32 "
        "{%0,%1,%2,%3}, {%4,%5,%6,%7}, {%8,%9}, {%0,%1,%2,%3};"
        : "+f"(c[0]), "+f"(c[1]), "+f"(c[2]), "+f"(c[3])
        : "r"(a[0]), "r"(a[1]), "r"(a[2]), "r"(a[3]), "r"(b0), "r"(b1));
}

__device__ __forceinline__ void stage_chunk(uint32_t sb, int base,
                                            int m0, int n0, int k0, int tid) {
#pragma unroll
    for (int q = 0; q < 4; ++q) {
        int job = q * 256 + tid;
        int row = job >> 3, kg = job & 7;
        size_t src = (size_t)(m0 + row) * DD + k0 + kg * 8;
        int off = base + row * XP_STRIDE_B + kg * 16;
        cp16(sb + XP_AHI + off, g_xhi + src);
        cp16(sb + XP_ALO + off, g_xlo + src);
    }
#pragma unroll
    for (int q = 0; q < 4; ++q) {
        int job = q * 256 + tid;
        int row = job >> 3, kg = job & 7;
        size_t src = (size_t)(n0 + row) * DD + k0 + kg * 8;
        int off = base + row * XP_STRIDE_B + kg * 16;
        cp16(sb + XP_WHI + off, g_whi + src);
        cp16(sb + XP_WLO + off, g_wlo + src);
    }
}

__global__ __launch_bounds__(256) void xproj_mma_kernel(
    const float* __restrict__ bx,
    float* __restrict__ C)
{
    extern __shared__ char smem[];
    const uint32_t sb = smem_u32(smem);
    const int tid = threadIdx.x;
    const int wid = tid >> 5;
    const int l   = tid & 31;
    const int warp_m = wid & 3;
    const int warp_n = wid >> 2;
    const int m0 = blockIdx.x * 128;
    const int n0 = blockIdx.y * 128;

    float acc[2][8][4];
#pragma unroll
    for (int t = 0; t < 2; t++)
#pragma unroll
        for (int nb = 0; nb < 8; nb++)
#pragma unroll
            for (int i = 0; i < 4; i++) acc[t][nb][i] = 0.0f;

    const uint32_t aRowOff = (uint32_t)((warp_m * 32 + (l & 15)) * XP_STRIDE_B +
                                        (l >> 4) * 16);
    const uint32_t bRowOff = (uint32_t)((warp_n * 64 + ((l >> 4) << 3) + (l & 7)) * XP_STRIDE_B +
                                        ((l >> 3) & 1) * 16);

    stage_chunk(sb, 0, m0, n0, 0, tid);
    CP_COMMIT();

#pragma unroll
    for (int c = 0; c < 4; ++c) {
        if (c < 3) {
            stage_chunk(sb, ((c + 1) & 1) * XP_SMEM, m0, n0, (c + 1) * 64, tid);
            CP_COMMIT();
            cp_wait<1>();
        } else {
            cp_wait<0>();
        }
        __syncthreads();

        const uint32_t base = (uint32_t)((c & 1) * XP_SMEM);
#pragma unroll
        for (int ks = 0; ks < 4; ++ks) {
            const uint32_t kOff = (uint32_t)(ks * 32);
            uint32_t ahi[2][4], alo[2][4];
#pragma unroll
            for (int t = 0; t < 2; t++) {
                uint32_t abase = base + aRowOff + (uint32_t)(t * 16 * XP_STRIDE_B) + kOff;
                ldm_x4(ahi[t][0], ahi[t][1], ahi[t][2], ahi[t][3], sb + XP_AHI + abase);
                ldm_x4(alo[t][0], alo[t][1], alo[t][2], alo[t][3], sb + XP_ALO + abase);
            }
#pragma unroll
            for (int g = 0; g < 4; ++g) {
                uint32_t bbase = base + bRowOff + (uint32_t)(g * 16 * XP_STRIDE_B) + kOff;
                uint32_t h0, h1, h2, h3, q0, q1, q2, q3;
                ldm_x4(h0, h1, h2, h3, sb + XP_WHI + bbase);
                ldm_x4(q0, q1, q2, q3, sb + XP_WLO + bbase);
#pragma unroll
                for (int t = 0; t < 2; t++) {
                    mma16816(acc[t][2 * g],     ahi[t], h0, h1);
                    mma16816(acc[t][2 * g + 1], ahi[t], h2, h3);
                    mma16816(acc[t][2 * g],     alo[t], h0, h1);
                    mma16816(acc[t][2 * g + 1], alo[t], h2, h3);
                    mma16816(acc[t][2 * g],     ahi[t], q0, q1);
                    mma16816(acc[t][2 * g + 1], ahi[t], q2, q3);
                }
            }
        }
        __syncthreads();
    }

    const int mrow = m0 + warp_m * 32 + (l >> 2);
    const int ncol = n0 + warp_n * 64 + 2 * (l & 3);
#pragma unroll
    for (int t = 0; t < 2; t++) {
#pragma unroll
        for (int nb = 0; nb < 8; nb++) {
            int nn = ncol + nb * 8;
            float2 bv = *(const float2*)(bx + nn);
            int r0 = mrow + t * 16;
            float2 o0 = make_float2(acc[t][nb][0] + bv.x, acc[t][nb][1] + bv.y);
            float2 o1 = make_float2(acc[t][nb][2] + bv.x, acc[t][nb][3] + bv.y);
            *(float2*)(C + (size_t)r0 * HH + nn) = o0;
            *(float2*)(C + (size_t)(r0 + 8) * HH + nn) = o1;
        }
    }
}

// ====================================================================
// Kernel 2: scan v6 — R10 structure (lane-paired, 1 barrier/step) +
//   fast exp-based tanh + packed f32x2 reduction.
// ====================================================================
#define HPAD 264   // 128 + 8 + 128 floats per h snapshot

__global__ __launch_bounds__(512, 1) void scan_kernel(
    const float* __restrict__ h0,
    const float* __restrict__ Wh,
    const float* __restrict__ bh,
    float* __restrict__ out,
    int hasFinal)
{
    extern __shared__ float smemf[];
    float4* Wsm  = (float4*)smemf;           // [8][512] float4 = 64 KB
    float*  hbuf = smemf + 8 * 512 * 4;      // 2 * HPAD floats (ping-pong)

    const int tid  = threadIdx.x;
    const int j    = tid >> 1;
    const int half = tid & 1;
    const int b    = blockIdx.x;
    const int kb   = half * 128;

    // register-resident weights: k in [kb, kb+96) as 48 packed f32x2 pairs
    ulonglong2 wu[24];
    const ulonglong2* wrow = (const ulonglong2*)(Wh + (size_t)j * HH + kb);
#pragma unroll
    for (int i = 0; i < 24; i++) wu[i] = wrow[i];

    // smem weights: k in [kb+96, kb+128), laid out [g][tid] (conflict-free)
    const float4* wrow4 = (const float4*)(Wh + (size_t)j * HH + kb);
#pragma unroll
    for (int g = 0; g < 8; ++g)
        Wsm[g * 512 + tid] = wrow4[24 + g];

    if (tid < 256) {
        int pos = tid + ((tid >> 7) << 3);   // +8 pad for upper half
        hbuf[pos] = h0[(size_t)b * HH + tid];
    }
    const float bh_r = bh[j];
    float* const outp = out + (size_t)b * HH + j;   // step stride BB*HH

    float xp_next = outp[0];
    __syncthreads();

    const int hpos = j + ((j >> 7) << 3);
    int cur = 0;
    for (int t = 0; t < LL; ++t) {
        const float xp = xp_next;
        if (t + 1 < LL) xp_next = outp[(size_t)(t + 1) * (BB * HH)];

        const ulonglong2* h2 = (const ulonglong2*)(hbuf + cur * HPAD + half * 136);
        unsigned long long p0 = 0ULL, p1 = 0ULL, p2 = 0ULL, p3 = 0ULL;
#pragma unroll
        for (int i = 0; i < 24; i++) {
            ulonglong2 hv = h2[i];
            p0 = ffma2(wu[i].x, hv.x, p0);
            p1 = ffma2(wu[i].y, hv.y, p1);
        }
        const ulonglong2* ws2 = (const ulonglong2*)Wsm;
#pragma unroll
        for (int g = 0; g < 8; g++) {
            ulonglong2 wv = ws2[(size_t)g * 512 + tid];
            ulonglong2 hv = h2[24 + g];
            p2 = ffma2(wv.x, hv.x, p2);
            p3 = ffma2(wv.y, hv.y, p3);
        }
        float acc = upk_sum(addf2(addf2(p0, p1), addf2(p2, p3)));
        float other = __shfl_xor_sync(0xFFFFFFFFu, acc, 1);
        float hn = fast_tanh(acc + other + xp + bh_r);

        if (!half) {
            hbuf[(cur ^ 1) * HPAD + hpos] = hn;
        } else {
            outp[(size_t)t * (BB * HH)] = hn;
            if (hasFinal && t == LL - 1)
                outp[(size_t)LL * (BB * HH)] = hn;
        }
        __syncthreads();
        cur ^= 1;
    }
}

// ====================================================================
// launch
// ====================================================================
extern "C" void kernel_launch(void* const* d_in, const int* in_sizes, int n_in,
                              void* d_out, int out_size)
{
    const float* x   = (const float*)d_in[0];
    const float* h0  = (const float*)d_in[1];
    const float* Wxw = (const float*)d_in[2];
    const float* Wxb = (const float*)d_in[3];
    const float* Whw = (const float*)d_in[4];
    const float* Whb = (const float*)d_in[5];
    float* out = (float*)d_out;

    (void)in_sizes; (void)n_in;

    cudaFuncSetAttribute(xproj_mma_kernel, cudaFuncAttributeMaxDynamicSharedMemorySize, XP_SMEM2);
    const int smemScan = (8 * 512 * 4 + 2 * HPAD) * (int)sizeof(float);
    cudaFuncSetAttribute(scan_kernel, cudaFuncAttributeMaxDynamicSharedMemorySize, smemScan);

    convert_kernel<<<(CV_JOBS + 255) / 256, 256>>>(x, Wxw);

    dim3 g1(LL * BB / 128, HH / 128);   // (1024, 2)
    xproj_mma_kernel<<<g1, 256, XP_SMEM2>>>(Wxb, out);

    const int hasFinal = (out_size >= LL * BB * HH + BB * HH) ? 1 : 0;
    scan_kernel<<<BB, 512, smemScan>>>(h0, Whw, Whb, out, hasFinal);
}

// round 12
// speedup vs baseline: 1.5337x; 1.5337x over previous
#include <cuda_runtime.h>
#include <cuda_bf16.h>
#include <math.h>
#include <stdint.h>

#define LL 1024
#define BB 128
#define DD 256
#define HH 256

#define XN (LL * BB * DD)
#define WN (HH * DD)

// Pre-split bf16 scratch (static device arrays — allowed)
__device__ __align__(16) __nv_bfloat16 g_xhi[XN];
__device__ __align__(16) __nv_bfloat16 g_xlo[XN];
__device__ __align__(16) __nv_bfloat16 g_whi[WN];
__device__ __align__(16) __nv_bfloat16 g_wlo[WN];

__device__ __forceinline__ uint32_t smem_u32(const void* p) {
    uint32_t a;
    asm("{ .reg .u64 t; cvta.to.shared.u64 t, %1; cvt.u32.u64 %0, t; }"
        : "=r"(a) : "l"(p));
    return a;
}

// Packed f32x2 ops
__device__ __forceinline__ unsigned long long ffma2(
    unsigned long long a, unsigned long long b, unsigned long long c)
{
    unsigned long long d;
    asm("fma.rn.f32x2 %0, %1, %2, %3;" : "=l"(d) : "l"(a), "l"(b), "l"(c));
    return d;
}
__device__ __forceinline__ unsigned long long addf2(
    unsigned long long a, unsigned long long b)
{
    unsigned long long d;
    asm("add.rn.f32x2 %0, %1, %2;" : "=l"(d) : "l"(a), "l"(b));
    return d;
}
__device__ __forceinline__ float upk_sum(unsigned long long p)
{
    float lo, hi;
    asm("mov.b64 {%0, %1}, %2;" : "=f"(lo), "=f"(hi) : "l"(p));
    return lo + hi;
}

// fast tanh: 1 - 2/(e^{2x}+1); exact at saturations, rel err ~1e-6
__device__ __forceinline__ float fast_tanh(float x)
{
    float e = __expf(x + x);
    float r;
    asm("rcp.approx.f32 %0, %1;" : "=f"(r) : "f"(e + 1.0f));
    return fmaf(-2.0f, r, 1.0f);
}

__device__ __forceinline__ void split2(float a, float b, uint32_t& h, uint32_t& l) {
    __nv_bfloat16 ha = __float2bfloat16(a);
    __nv_bfloat16 hb = __float2bfloat16(b);
    float ra = a - __bfloat162float(ha);
    float rb = b - __bfloat162float(hb);
    __nv_bfloat16 la = __float2bfloat16(ra);
    __nv_bfloat16 lb = __float2bfloat16(rb);
    h = (uint32_t)reinterpret_cast<unsigned short&>(ha) |
        ((uint32_t)reinterpret_cast<unsigned short&>(hb) << 16);
    l = (uint32_t)reinterpret_cast<unsigned short&>(la) |
        ((uint32_t)reinterpret_cast<unsigned short&>(lb) << 16);
}

// ====================================================================
// Kernel 0: one-shot fp32 -> split-bf16 (hi, lo) for X and Wx.
// ====================================================================
#define CV_JOBS ((XN + WN) / 4)

__global__ __launch_bounds__(256) void convert_kernel(
    const float* __restrict__ X, const float* __restrict__ Wx)
{
    int i = blockIdx.x * 256 + threadIdx.x;
    if (i >= CV_JOBS) return;
    float4 v;
    if (i < XN / 4) v = ((const float4*)X)[i];
    else            v = ((const float4*)Wx)[i - XN / 4];
    uint2 hi, lo;
    split2(v.x, v.y, hi.x, lo.x);
    split2(v.z, v.w, hi.y, lo.y);
    if (i < XN / 4) {
        *(uint2*)(g_xhi + (size_t)i * 4) = hi;
        *(uint2*)(g_xlo + (size_t)i * 4) = lo;
    } else {
        size_t o = (size_t)(i - XN / 4) * 4;
        *(uint2*)(g_whi + o) = hi;
        *(uint2*)(g_wlo + o) = lo;
    }
}

// ====================================================================
// Kernel 1: xproj GEMM via mma.sync bf16 split-3 (R10 version, known good).
// ====================================================================
#define XP_STRIDE_B 144
#define XP_TILE_B   (128 * XP_STRIDE_B)
#define XP_AHI 0
#define XP_ALO XP_TILE_B
#define XP_WHI (2 * XP_TILE_B)
#define XP_WLO (3 * XP_TILE_B)
#define XP_SMEM (4 * XP_TILE_B)

__device__ __forceinline__ void ldm_x4(uint32_t& r0, uint32_t& r1,
                                       uint32_t& r2, uint32_t& r3, uint32_t addr) {
    asm volatile("ldmatrix.sync.aligned.m8n8.x4.shared.b16 {%0,%1,%2,%3}, [%4];"
                 : "=r"(r0), "=r"(r1), "=r"(r2), "=r"(r3) : "r"(addr));
}

__device__ __forceinline__ void mma16816(float* c, const uint32_t* a,
                                         uint32_t b0, uint32_t b1) {
    asm volatile(
        "mma.sync.aligned.m16n8k16.row.col.f32.bf16.bf16.f32 "
        "{%0,%1,%2,%3}, {%4,%5,%6,%7}, {%8,%9}, {%0,%1,%2,%3};"
        : "+f"(c[0]), "+f"(c[1]), "+f"(c[2]), "+f"(c[3])
        : "r"(a[0]), "r"(a[1]), "r"(a[2]), "r"(a[3]), "r"(b0), "r"(b1));
}

__global__ __launch_bounds__(256) void xproj_mma_kernel(
    const float* __restrict__ bx,
    float* __restrict__ C)
{
    extern __shared__ char smem[];
    const uint32_t sb = smem_u32(smem);
    const int tid = threadIdx.x;
    const int wid = tid >> 5;
    const int l   = tid & 31;
    const int warp_m = wid & 3;
    const int warp_n = wid >> 2;
    const int m0 = blockIdx.x * 128;
    const int n0 = blockIdx.y * 128;

    float acc[2][8][4];
#pragma unroll
    for (int t = 0; t < 2; t++)
#pragma unroll
        for (int nb = 0; nb < 8; nb++)
#pragma unroll
            for (int i = 0; i < 4; i++) acc[t][nb][i] = 0.0f;

    const uint32_t aRowOff = (uint32_t)((warp_m * 32 + (l & 15)) * XP_STRIDE_B +
                                        (l >> 4) * 16);
    const uint32_t bRowOff = (uint32_t)((warp_n * 64 + ((l >> 4) << 3) + (l & 7)) * XP_STRIDE_B +
                                        ((l >> 3) & 1) * 16);

    for (int c = 0; c < 4; ++c) {
        const int k0 = c * 64;
#pragma unroll
        for (int q = 0; q < 4; ++q) {
            int job = q * 256 + tid;
            int row = job >> 3, kg = job & 7;
            size_t src = (size_t)(m0 + row) * DD + k0 + kg * 8;
            int off = row * XP_STRIDE_B + kg * 16;
            *(uint4*)(smem + XP_AHI + off) = *(const uint4*)(g_xhi + src);
            *(uint4*)(smem + XP_ALO + off) = *(const uint4*)(g_xlo + src);
        }
#pragma unroll
        for (int q = 0; q < 4; ++q) {
            int job = q * 256 + tid;
            int row = job >> 3, kg = job & 7;
            size_t src = (size_t)(n0 + row) * DD + k0 + kg * 8;
            int off = row * XP_STRIDE_B + kg * 16;
            *(uint4*)(smem + XP_WHI + off) = *(const uint4*)(g_whi + src);
            *(uint4*)(smem + XP_WLO + off) = *(const uint4*)(g_wlo + src);
        }
        __syncthreads();

#pragma unroll
        for (int ks = 0; ks < 4; ++ks) {
            const uint32_t kOff = (uint32_t)(ks * 32);
            uint32_t ahi[2][4], alo[2][4];
#pragma unroll
            for (int t = 0; t < 2; t++) {
                uint32_t abase = aRowOff + (uint32_t)(t * 16 * XP_STRIDE_B) + kOff;
                ldm_x4(ahi[t][0], ahi[t][1], ahi[t][2], ahi[t][3], sb + XP_AHI + abase);
                ldm_x4(alo[t][0], alo[t][1], alo[t][2], alo[t][3], sb + XP_ALO + abase);
            }
#pragma unroll
            for (int g = 0; g < 4; ++g) {
                uint32_t bbase = bRowOff + (uint32_t)(g * 16 * XP_STRIDE_B) + kOff;
                uint32_t h0, h1, h2, h3, q0, q1, q2, q3;
                ldm_x4(h0, h1, h2, h3, sb + XP_WHI + bbase);
                ldm_x4(q0, q1, q2, q3, sb + XP_WLO + bbase);
#pragma unroll
                for (int t = 0; t < 2; t++) {
                    mma16816(acc[t][2 * g],     ahi[t], h0, h1);
                    mma16816(acc[t][2 * g + 1], ahi[t], h2, h3);
                    mma16816(acc[t][2 * g],     alo[t], h0, h1);
                    mma16816(acc[t][2 * g + 1], alo[t], h2, h3);
                    mma16816(acc[t][2 * g],     ahi[t], q0, q1);
                    mma16816(acc[t][2 * g + 1], ahi[t], q2, q3);
                }
            }
        }
        __syncthreads();
    }

    const int mrow = m0 + warp_m * 32 + (l >> 2);
    const int ncol = n0 + warp_n * 64 + 2 * (l & 3);
#pragma unroll
    for (int t = 0; t < 2; t++) {
#pragma unroll
        for (int nb = 0; nb < 8; nb++) {
            int nn = ncol + nb * 8;
            float2 bv = *(const float2*)(bx + nn);
            int r0 = mrow + t * 16;
            float2 o0 = make_float2(acc[t][nb][0] + bv.x, acc[t][nb][1] + bv.y);
            float2 o1 = make_float2(acc[t][nb][2] + bv.x, acc[t][nb][3] + bv.y);
            *(float2*)(C + (size_t)r0 * HH + nn) = o0;
            *(float2*)(C + (size_t)(r0 + 8) * HH + nn) = o1;
        }
    }
}

// ====================================================================
// Kernel 2: scan v6 — lane-paired halves, shuffle combine, 1 barrier/step,
//   fast exp-based tanh + packed f32x2 reduction (kept from R11).
// ====================================================================
#define HPAD 264   // 128 + 8 + 128 floats per h snapshot

__global__ __launch_bounds__(512, 1) void scan_kernel(
    const float* __restrict__ h0,
    const float* __restrict__ Wh,
    const float* __restrict__ bh,
    float* __restrict__ out,
    int hasFinal)
{
    extern __shared__ float smemf[];
    float4* Wsm  = (float4*)smemf;           // [8][512] float4 = 64 KB
    float*  hbuf = smemf + 8 * 512 * 4;      // 2 * HPAD floats (ping-pong)

    const int tid  = threadIdx.x;
    const int j    = tid >> 1;
    const int half = tid & 1;
    const int b    = blockIdx.x;
    const int kb   = half * 128;

    // register-resident weights: k in [kb, kb+96) as 48 packed f32x2 pairs
    ulonglong2 wu[24];
    const ulonglong2* wrow = (const ulonglong2*)(Wh + (size_t)j * HH + kb);
#pragma unroll
    for (int i = 0; i < 24; i++) wu[i] = wrow[i];

    // smem weights: k in [kb+96, kb+128), laid out [g][tid] (conflict-free)
    const float4* wrow4 = (const float4*)(Wh + (size_t)j * HH + kb);
#pragma unroll
    for (int g = 0; g < 8; ++g)
        Wsm[g * 512 + tid] = wrow4[24 + g];

    if (tid < 256) {
        int pos = tid + ((tid >> 7) << 3);   // +8 pad for upper half
        hbuf[pos] = h0[(size_t)b * HH + tid];
    }
    const float bh_r = bh[j];
    float* const outp = out + (size_t)b * HH + j;   // step stride BB*HH

    float xp_next = outp[0];
    __syncthreads();

    const int hpos = j + ((j >> 7) << 3);
    int cur = 0;
    for (int t = 0; t < LL; ++t) {
        const float xp = xp_next;
        if (t + 1 < LL) xp_next = outp[(size_t)(t + 1) * (BB * HH)];

        const ulonglong2* h2 = (const ulonglong2*)(hbuf + cur * HPAD + half * 136);
        unsigned long long p0 = 0ULL, p1 = 0ULL, p2 = 0ULL, p3 = 0ULL;
#pragma unroll
        for (int i = 0; i < 24; i++) {
            ulonglong2 hv = h2[i];
            p0 = ffma2(wu[i].x, hv.x, p0);
            p1 = ffma2(wu[i].y, hv.y, p1);
        }
        const ulonglong2* ws2 = (const ulonglong2*)Wsm;
#pragma unroll
        for (int g = 0; g < 8; g++) {
            ulonglong2 wv = ws2[(size_t)g * 512 + tid];
            ulonglong2 hv = h2[24 + g];
            p2 = ffma2(wv.x, hv.x, p2);
            p3 = ffma2(wv.y, hv.y, p3);
        }
        float acc = upk_sum(addf2(addf2(p0, p1), addf2(p2, p3)));
        float other = __shfl_xor_sync(0xFFFFFFFFu, acc, 1);
        float hn = fast_tanh(acc + other + xp + bh_r);

        if (!half) {
            hbuf[(cur ^ 1) * HPAD + hpos] = hn;
        } else {
            outp[(size_t)t * (BB * HH)] = hn;
            if (hasFinal && t == LL - 1)
                outp[(size_t)LL * (BB * HH)] = hn;
        }
        __syncthreads();
        cur ^= 1;
    }
}

// ====================================================================
// launch
// ====================================================================
extern "C" void kernel_launch(void* const* d_in, const int* in_sizes, int n_in,
                              void* d_out, int out_size)
{
    const float* x   = (const float*)d_in[0];
    const float* h0  = (const float*)d_in[1];
    const float* Wxw = (const float*)d_in[2];
    const float* Wxb = (const float*)d_in[3];
    const float* Whw = (const float*)d_in[4];
    const float* Whb = (const float*)d_in[5];
    float* out = (float*)d_out;

    (void)in_sizes; (void)n_in;

    cudaFuncSetAttribute(xproj_mma_kernel, cudaFuncAttributeMaxDynamicSharedMemorySize, XP_SMEM);
    const int smemScan = (8 * 512 * 4 + 2 * HPAD) * (int)sizeof(float);
    cudaFuncSetAttribute(scan_kernel, cudaFuncAttributeMaxDynamicSharedMemorySize, smemScan);

    convert_kernel<<<(CV_JOBS + 255) / 256, 256>>>(x, Wxw);

    dim3 g1(LL * BB / 128, HH / 128);   // (1024, 2)
    xproj_mma_kernel<<<g1, 256, XP_SMEM>>>(Wxb, out);

    const int hasFinal = (out_size >= LL * BB * HH + BB * HH) ? 1 : 0;
    scan_kernel<<<BB, 512, smemScan>>>(h0, Whw, Whb, out, hasFinal);
}

// round 13
// speedup vs baseline: 1.6496x; 1.0756x over previous
#include <cuda_runtime.h>
#include <cuda_bf16.h>
#include <math.h>
#include <stdint.h>

#define LL 1024
#define BB 128
#define DD 256
#define HH 256

#define XN (LL * BB * DD)
#define WN (HH * DD)

// Pre-split bf16 scratch (static device arrays — allowed)
__device__ __align__(16) __nv_bfloat16 g_xhi[XN];
__device__ __align__(16) __nv_bfloat16 g_xlo[XN];
__device__ __align__(16) __nv_bfloat16 g_whi[WN];
__device__ __align__(16) __nv_bfloat16 g_wlo[WN];

__device__ __forceinline__ uint32_t smem_u32(const void* p) {
    uint32_t a;
    asm("{ .reg .u64 t; cvta.to.shared.u64 t, %1; cvt.u32.u64 %0, t; }"
        : "=r"(a) : "l"(p));
    return a;
}

// Packed f32x2 FMA
__device__ __forceinline__ unsigned long long ffma2(
    unsigned long long a, unsigned long long b, unsigned long long c)
{
    unsigned long long d;
    asm("fma.rn.f32x2 %0, %1, %2, %3;" : "=l"(d) : "l"(a), "l"(b), "l"(c));
    return d;
}
__device__ __forceinline__ float upk_sum(unsigned long long p)
{
    float lo, hi;
    asm("mov.b64 {%0, %1}, %2;" : "=f"(lo), "=f"(hi) : "l"(p));
    return lo + hi;
}

__device__ __forceinline__ void split2(float a, float b, uint32_t& h, uint32_t& l) {
    __nv_bfloat16 ha = __float2bfloat16(a);
    __nv_bfloat16 hb = __float2bfloat16(b);
    float ra = a - __bfloat162float(ha);
    float rb = b - __bfloat162float(hb);
    __nv_bfloat16 la = __float2bfloat16(ra);
    __nv_bfloat16 lb = __float2bfloat16(rb);
    h = (uint32_t)reinterpret_cast<unsigned short&>(ha) |
        ((uint32_t)reinterpret_cast<unsigned short&>(hb) << 16);
    l = (uint32_t)reinterpret_cast<unsigned short&>(la) |
        ((uint32_t)reinterpret_cast<unsigned short&>(lb) << 16);
}

// cp.async helpers
__device__ __forceinline__ void cp16(uint32_t s, const void* g) {
    asm volatile("cp.async.cg.shared.global [%0], [%1], 16;" :: "r"(s), "l"(g));
}
#define CP_COMMIT() asm volatile("cp.async.commit_group;" ::: "memory")
template <int N>
__device__ __forceinline__ void cp_wait() {
    asm volatile("cp.async.wait_group %0;" :: "n"(N) : "memory");
}

// ====================================================================
// Kernel 0: one-shot fp32 -> split-bf16 (hi, lo) for X and Wx.
// ====================================================================
#define CV_JOBS ((XN + WN) / 4)

__global__ __launch_bounds__(256) void convert_kernel(
    const float* __restrict__ X, const float* __restrict__ Wx)
{
    int i = blockIdx.x * 256 + threadIdx.x;
    if (i >= CV_JOBS) return;
    float4 v;
    if (i < XN / 4) v = ((const float4*)X)[i];
    else            v = ((const float4*)Wx)[i - XN / 4];
    uint2 hi, lo;
    split2(v.x, v.y, hi.x, lo.x);
    split2(v.z, v.w, hi.y, lo.y);
    if (i < XN / 4) {
        *(uint2*)(g_xhi + (size_t)i * 4) = hi;
        *(uint2*)(g_xlo + (size_t)i * 4) = lo;
    } else {
        size_t o = (size_t)(i - XN / 4) * 4;
        *(uint2*)(g_whi + o) = hi;
        *(uint2*)(g_wlo + o) = lo;
    }
}

// ====================================================================
// Kernel 1: xproj GEMM, mma.sync bf16 split-3, sub-chunk double-buffered
//   cp.async pipeline. K split into 8 sub-chunks of 32; two 40KB buffers
//   (80KB total) keep 2 CTAs/SM while staging overlaps MMA.
//   Row stride 80B (64B data + 16B pad): 16B-aligned, ldmatrix conflict-free.
// ====================================================================
#define SC_K   32                        // k per sub-chunk
#define NSC    8                         // number of sub-chunks
#define ST_B   80                        // bytes per staged row
#define ST_TILE (128 * ST_B)             // 10240
#define SB_AHI 0
#define SB_ALO ST_TILE
#define SB_WHI (2 * ST_TILE)
#define SB_WLO (3 * ST_TILE)
#define SB_BUF (4 * ST_TILE)             // 40960 per buffer
#define XP_SMEM (2 * SB_BUF)             // 81920

__device__ __forceinline__ void ldm_x4(uint32_t& r0, uint32_t& r1,
                                       uint32_t& r2, uint32_t& r3, uint32_t addr) {
    asm volatile("ldmatrix.sync.aligned.m8n8.x4.shared.b16 {%0,%1,%2,%3}, [%4];"
                 : "=r"(r0), "=r"(r1), "=r"(r2), "=r"(r3) : "r"(addr));
}

__device__ __forceinline__ void mma16816(float* c, const uint32_t* a,
                                         uint32_t b0, uint32_t b1) {
    asm volatile(
        "mma.sync.aligned.m16n8k16.row.col.f32.bf16.bf16.f32 "
        "{%0,%1,%2,%3}, {%4,%5,%6,%7}, {%8,%9}, {%0,%1,%2,%3};"
        : "+f"(c[0]), "+f"(c[1]), "+f"(c[2]), "+f"(c[3])
        : "r"(a[0]), "r"(a[1]), "r"(a[2]), "r"(a[3]), "r"(b0), "r"(b1));
}

// stage one 32-k sub-chunk into buffer at bufbase (8 cp.async per thread)
__device__ __forceinline__ void stage_sc(uint32_t sb, uint32_t bufbase,
                                         int m0, int n0, int k0, int tid) {
#pragma unroll
    for (int q = 0; q < 2; ++q) {
        int job = q * 256 + tid;
        int row = job >> 2, kg = job & 3;
        size_t src = (size_t)(m0 + row) * DD + k0 + kg * 8;
        uint32_t off = bufbase + (uint32_t)(row * ST_B + kg * 16);
        cp16(sb + SB_AHI + off, g_xhi + src);
        cp16(sb + SB_ALO + off, g_xlo + src);
    }
#pragma unroll
    for (int q = 0; q < 2; ++q) {
        int job = q * 256 + tid;
        int row = job >> 2, kg = job & 3;
        size_t src = (size_t)(n0 + row) * DD + k0 + kg * 8;
        uint32_t off = bufbase + (uint32_t)(row * ST_B + kg * 16);
        cp16(sb + SB_WHI + off, g_whi + src);
        cp16(sb + SB_WLO + off, g_wlo + src);
    }
}

__global__ __launch_bounds__(256) void xproj_mma_kernel(
    const float* __restrict__ bx,
    float* __restrict__ C)
{
    extern __shared__ char smem[];
    const uint32_t sb = smem_u32(smem);
    const int tid = threadIdx.x;
    const int wid = tid >> 5;
    const int l   = tid & 31;
    const int warp_m = wid & 3;
    const int warp_n = wid >> 2;
    const int m0 = blockIdx.x * 128;
    const int n0 = blockIdx.y * 128;

    float acc[2][8][4];
#pragma unroll
    for (int t = 0; t < 2; t++)
#pragma unroll
        for (int nb = 0; nb < 8; nb++)
#pragma unroll
            for (int i = 0; i < 4; i++) acc[t][nb][i] = 0.0f;

    const uint32_t aRowOff = (uint32_t)((warp_m * 32 + (l & 15)) * ST_B +
                                        (l >> 4) * 16);
    const uint32_t bRowOff = (uint32_t)((warp_n * 64 + ((l >> 4) << 3) + (l & 7)) * ST_B +
                                        ((l >> 3) & 1) * 16);

    stage_sc(sb, 0, m0, n0, 0, tid);
    CP_COMMIT();

#pragma unroll
    for (int sc = 0; sc < NSC; ++sc) {
        if (sc < NSC - 1) {
            stage_sc(sb, (uint32_t)(((sc + 1) & 1) * SB_BUF), m0, n0,
                     (sc + 1) * SC_K, tid);
            CP_COMMIT();
            cp_wait<1>();
        } else {
            cp_wait<0>();
        }
        __syncthreads();

        const uint32_t base = (uint32_t)((sc & 1) * SB_BUF);
#pragma unroll
        for (int ks = 0; ks < 2; ++ks) {
            const uint32_t kOff = (uint32_t)(ks * 32);
            uint32_t ahi[2][4], alo[2][4];
#pragma unroll
            for (int t = 0; t < 2; t++) {
                uint32_t abase = base + aRowOff + (uint32_t)(t * 16 * ST_B) + kOff;
                ldm_x4(ahi[t][0], ahi[t][1], ahi[t][2], ahi[t][3], sb + SB_AHI + abase);
                ldm_x4(alo[t][0], alo[t][1], alo[t][2], alo[t][3], sb + SB_ALO + abase);
            }
#pragma unroll
            for (int g = 0; g < 4; ++g) {
                uint32_t bbase = base + bRowOff + (uint32_t)(g * 16 * ST_B) + kOff;
                uint32_t h0, h1, h2, h3, q0, q1, q2, q3;
                ldm_x4(h0, h1, h2, h3, sb + SB_WHI + bbase);
                ldm_x4(q0, q1, q2, q3, sb + SB_WLO + bbase);
#pragma unroll
                for (int t = 0; t < 2; t++) {
                    mma16816(acc[t][2 * g],     ahi[t], h0, h1);
                    mma16816(acc[t][2 * g + 1], ahi[t], h2, h3);
                    mma16816(acc[t][2 * g],     alo[t], h0, h1);
                    mma16816(acc[t][2 * g + 1], alo[t], h2, h3);
                    mma16816(acc[t][2 * g],     ahi[t], q0, q1);
                    mma16816(acc[t][2 * g + 1], ahi[t], q2, q3);
                }
            }
        }
        __syncthreads();
    }

    const int mrow = m0 + warp_m * 32 + (l >> 2);
    const int ncol = n0 + warp_n * 64 + 2 * (l & 3);
#pragma unroll
    for (int t = 0; t < 2; t++) {
#pragma unroll
        for (int nb = 0; nb < 8; nb++) {
            int nn = ncol + nb * 8;
            float2 bv = *(const float2*)(bx + nn);
            int r0 = mrow + t * 16;
            float2 o0 = make_float2(acc[t][nb][0] + bv.x, acc[t][nb][1] + bv.y);
            float2 o1 = make_float2(acc[t][nb][2] + bv.x, acc[t][nb][3] + bv.y);
            *(float2*)(C + (size_t)r0 * HH + nn) = o0;
            *(float2*)(C + (size_t)(r0 + 8) * HH + nn) = o1;
        }
    }
}

// ====================================================================
// Kernel 2: scan (exact R10 version — best measured at 1233 total).
// Lane-paired halves, shuffle combine, 1 barrier/step, padded hbuf.
// ====================================================================
#define HPAD 264   // 128 + 8 + 128 floats per h snapshot

__global__ __launch_bounds__(512, 1) void scan_kernel(
    const float* __restrict__ h0,
    const float* __restrict__ Wh,
    const float* __restrict__ bh,
    float* __restrict__ out,
    int hasFinal)
{
    extern __shared__ float smemf[];
    float4* Wsm  = (float4*)smemf;           // [8][512] float4 = 64 KB
    float*  hbuf = smemf + 8 * 512 * 4;      // 2 * HPAD floats (ping-pong)

    const int tid  = threadIdx.x;
    const int j    = tid >> 1;
    const int half = tid & 1;
    const int b    = blockIdx.x;
    const int kb   = half * 128;

    ulonglong2 wu[24];
    const ulonglong2* wrow = (const ulonglong2*)(Wh + (size_t)j * HH + kb);
#pragma unroll
    for (int i = 0; i < 24; i++) wu[i] = wrow[i];

    const float4* wrow4 = (const float4*)(Wh + (size_t)j * HH + kb);
#pragma unroll
    for (int g = 0; g < 8; ++g)
        Wsm[g * 512 + tid] = wrow4[24 + g];

    if (tid < 256) {
        int pos = tid + ((tid >> 7) << 3);   // +8 pad for upper half
        hbuf[pos] = h0[(size_t)b * HH + tid];
    }
    const float bh_r = bh[j];
    float* const outp = out + (size_t)b * HH + j;   // step stride BB*HH

    float xp_next = outp[0];
    __syncthreads();

    const int hpos = j + ((j >> 7) << 3);
    int cur = 0;
    for (int t = 0; t < LL; ++t) {
        const float xp = xp_next;
        if (t + 1 < LL) xp_next = outp[(size_t)(t + 1) * (BB * HH)];

        const ulonglong2* h2 = (const ulonglong2*)(hbuf + cur * HPAD + half * 136);
        unsigned long long p0 = 0ULL, p1 = 0ULL, p2 = 0ULL, p3 = 0ULL;
#pragma unroll
        for (int i = 0; i < 24; i++) {
            ulonglong2 hv = h2[i];
            p0 = ffma2(wu[i].x, hv.x, p0);
            p1 = ffma2(wu[i].y, hv.y, p1);
        }
        const ulonglong2* ws2 = (const ulonglong2*)Wsm;
#pragma unroll
        for (int g = 0; g < 8; g++) {
            ulonglong2 wv = ws2[(size_t)g * 512 + tid];
            ulonglong2 hv = h2[24 + g];
            p2 = ffma2(wv.x, hv.x, p2);
            p3 = ffma2(wv.y, hv.y, p3);
        }
        float acc = (upk_sum(p0) + upk_sum(p1)) + (upk_sum(p2) + upk_sum(p3));
        float other = __shfl_xor_sync(0xFFFFFFFFu, acc, 1);
        float hn = tanhf(acc + other + xp + bh_r);

        if (!half) {
            hbuf[(cur ^ 1) * HPAD + hpos] = hn;
        } else {
            outp[(size_t)t * (BB * HH)] = hn;
            if (hasFinal && t == LL - 1)
                outp[(size_t)LL * (BB * HH)] = hn;
        }
        __syncthreads();
        cur ^= 1;
    }
}

// ====================================================================
// launch
// ====================================================================
extern "C" void kernel_launch(void* const* d_in, const int* in_sizes, int n_in,
                              void* d_out, int out_size)
{
    const float* x   = (const float*)d_in[0];
    const float* h0  = (const float*)d_in[1];
    const float* Wxw = (const float*)d_in[2];
    const float* Wxb = (const float*)d_in[3];
    const float* Whw = (const float*)d_in[4];
    const float* Whb = (const float*)d_in[5];
    float* out = (float*)d_out;

    (void)in_sizes; (void)n_in;

    cudaFuncSetAttribute(xproj_mma_kernel, cudaFuncAttributeMaxDynamicSharedMemorySize, XP_SMEM);
    const int smemScan = (8 * 512 * 4 + 2 * HPAD) * (int)sizeof(float);
    cudaFuncSetAttribute(scan_kernel, cudaFuncAttributeMaxDynamicSharedMemorySize, smemScan);

    convert_kernel<<<(CV_JOBS + 255) / 256, 256>>>(x, Wxw);

    dim3 g1(LL * BB / 128, HH / 128);   // (1024, 2)
    xproj_mma_kernel<<<g1, 256, XP_SMEM>>>(Wxb, out);

    const int hasFinal = (out_size >= LL * BB * HH + BB * HH) ? 1 : 0;
    scan_kernel<<<BB, 512, smemScan>>>(h0, Whw, Whb, out, hasFinal);
}